// round 6
// baseline (speedup 1.0000x reference)
#include <cuda_runtime.h>
#include <math.h>

#define B_ 32
#define T_ 64
#define N_ 32
#define D_ 128
#define E_ 8
#define K_ 2
#define XT 68    // [feature][time] stride: 64 + 4 pad (16B aligned rows)
#define AT 132   // att_t [kt][row] stride: 128 + 4 pad (16B aligned)

typedef unsigned long long u64;

__device__ int   d_eidx[B_][K_];
__device__ float d_gateg[B_][K_];

// ---- f32x2 packed-math helpers ----
__device__ __forceinline__ u64 f2fma(u64 a, u64 b, u64 c) {
    u64 d; asm("fma.rn.f32x2 %0, %1, %2, %3;" : "=l"(d) : "l"(a), "l"(b), "l"(c)); return d;
}
__device__ __forceinline__ u64 f2mul(u64 a, u64 b) {
    u64 d; asm("mul.rn.f32x2 %0, %1, %2;" : "=l"(d) : "l"(a), "l"(b)); return d;
}
__device__ __forceinline__ u64 fpack(float lo, float hi) {
    u64 d; asm("mov.b64 %0, {%1, %2};" : "=l"(d) : "f"(lo), "f"(hi)); return d;
}
__device__ __forceinline__ u64 fdup(float v) { return fpack(v, v); }
__device__ __forceinline__ float2 funpack(u64 v) {
    float2 r; asm("mov.b64 {%0, %1}, %2;" : "=f"(r.x), "=f"(r.y) : "l"(v)); return r;
}

// ---------------------------------------------------------------------------
// Kernel 1: gating (eval mode)
// ---------------------------------------------------------------------------
__global__ void gate_kernel(const float* __restrict__ x,
                            const float* __restrict__ Wg) {
    const int b   = blockIdx.x;
    const int tid = threadIdx.x;  // 128 threads
    __shared__ float smean[D_];
    __shared__ float slog[E_];

    const float* xb = x + (size_t)b * T_ * N_ * D_;
    float s = 0.f;
    for (int i = 0; i < T_ * N_; ++i) s += xb[(size_t)i * D_ + tid];
    smean[tid] = s * (1.0f / (float)(T_ * N_));
    __syncthreads();

    if (tid < E_) {
        float l = 0.f;
        for (int d = 0; d < D_; ++d) l += smean[d] * Wg[d * E_ + tid];
        slog[tid] = l;
    }
    __syncthreads();

    if (tid == 0) {
        int i0 = 0; float v0 = slog[0];
        for (int e = 1; e < E_; ++e) if (slog[e] > v0) { v0 = slog[e]; i0 = e; }
        int i1 = -1; float v1 = -3.0e38f;
        for (int e = 0; e < E_; ++e) if (e != i0 && slog[e] > v1) { v1 = slog[e]; i1 = e; }
        const float e1  = expf(v1 - v0);
        const float inv = 1.0f / (1.0f + e1);
        d_eidx[b][0]  = i0; d_eidx[b][1]  = i1;
        d_gateg[b][0] = inv; d_gateg[b][1] = e1 * inv;
    }
}

// ---------------------------------------------------------------------------
// Kernel 2: one CTA per (b, n). 512 threads. Warp-local 2D sub-tiles so each
// weight LDG.128 touches one 128B line per warp and each LDS.128 is <=64B.
// SMEM: xs_t[128][68] | kst[128][68] (k_t / o_t) | vs[64][128] |
//       ar (att_t[64][132] then o1_t[128][68]) -> 34304 floats
// ---------------------------------------------------------------------------
__global__ __launch_bounds__(512, 1)
void moe_kernel(const float* __restrict__ x,
                const float* __restrict__ Wd,
                const float* __restrict__ bd,
                const float* __restrict__ Ws,
                const float* __restrict__ bs,
                float* __restrict__ out) {
    extern __shared__ float sm[];
    float* xs  = sm;             // 8704 floats  [d][t] stride 68
    float* kst = sm + 8704;      // 8704 floats  [feat][t] stride 68
    float* vs  = sm + 17408;     // 8192 floats  [t][feat]
    float* ar  = sm + 25600;     // 8704 floats  att_t[kt][row](132) / o1_t(68)

    const int n    = blockIdx.x;
    const int b    = blockIdx.y;
    const int tid  = threadIdx.x;
    const int lane = tid & 31;
    const int wid  = tid >> 5;

    // ---- load x slab [T][D] coalesced, store transposed xs_t[d][t] ----
    {
        const float4* xg = (const float4*)(x + ((size_t)b * T_ * N_ + n) * D_);
        #pragma unroll
        for (int i = tid; i < T_ * D_ / 4; i += 512) {
            const int t  = i >> 5;
            const int c4 = i & 31;
            float4 v = xg[(size_t)t * (N_ * D_ / 4) + c4];
            const int d0 = c4 * 4;
            xs[(d0 + 0) * XT + t] = v.x;
            xs[(d0 + 1) * XT + t] = v.y;
            xs[(d0 + 2) * XT + t] = v.z;
            xs[(d0 + 3) * XT + t] = v.w;
        }
    }

    // ---- shared warp-tile coordinates ----
    const int cq = lane & 7;     // col quad within warp
    const int rq = lane >> 3;    // row group within warp (0..3)

    // GEMM1 mapping: 8 k-warps + 8 v-warps, each 32 cols x 32 rows
    const int g1_isV  = wid >> 3;
    const int g1_colg = wid & 3;
    const int g1_rowg = (wid >> 2) & 1;
    const int g1_c0   = g1_colg * 32 + cq * 4;
    const int g1_r0   = g1_rowg * 32 + rq * 8;

    // GEMM2/3 + epilogue mapping: warp = 32 cols x 16 rows
    const int g2_c0 = (wid & 3) * 32 + cq * 4;
    const int g2_r0 = (wid >> 2) * 4 * 4 / 4;  // placeholder, computed below
    const int g2_row0 = (wid >> 2) * 16 + rq * 4;

    // att mapping: warp = 16 kt x 32 q-rows
    const int at_ktg = wid & 3;
    const int at_qg  = wid >> 2;          // 0..3 (2 per head)
    const int at_ktq = lane & 3;
    const int at_qq  = lane >> 2;         // 0..7
    const int at_kt0 = at_ktg * 16 + at_ktq * 4;
    const int at_hh  = at_qg >> 1;
    const int at_q0  = (at_qg & 1) * 32 + at_qq * 4;
    const int at_db  = at_hh * 64;

    // oGEMM mapping: warp = 32 dc x 16 t
    const int o_dcg = wid & 3;
    const int o_tg  = wid >> 2;
    const int o_dc0 = o_dcg * 32 + cq * 4;
    const int o_t0  = o_tg * 16 + rq * 4;
    const int o_rb  = (o_dcg >> 1) * 64 + o_t0;

    float accv[4][4];   // [col][row] for GEMM3/epilogue tile (g2 mapping)
    #pragma unroll
    for (int c = 0; c < 4; ++c)
        #pragma unroll
        for (int r = 0; r < 4; ++r) accv[c][r] = 0.f;

    __syncthreads();

    for (int slot = 0; slot < K_; ++slot) {
        const int   e = d_eidx[b][slot];
        const float g = d_gateg[b][slot];
        const float* Wm = Wd + ((size_t)(e * 2 + g1_isV) * N_ + n) * D_ * D_;
        const float* bm = bd + ((size_t)(e * 2 + g1_isV) * N_ + n) * D_;

        // ---- GEMM1: this warp computes k (isV=0) or v (isV=1), 32c x 32r ----
        {
            u64 acc[4][4];   // [col][rowpair] covering rows g1_r0..g1_r0+7
            const float4 bb = *(const float4*)&bm[g1_c0];
            #pragma unroll
            for (int p = 0; p < 4; ++p) {
                acc[0][p] = fdup(bb.x); acc[1][p] = fdup(bb.y);
                acc[2][p] = fdup(bb.z); acc[3][p] = fdup(bb.w);
            }
            #pragma unroll 4
            for (int d = 0; d < D_; ++d) {
                const ulonglong2 xa = *(const ulonglong2*)&xs[d * XT + g1_r0];
                const ulonglong2 xb2 = *(const ulonglong2*)&xs[d * XT + g1_r0 + 4];
                const float4 w = *(const float4*)&Wm[d * D_ + g1_c0];
                const u64 w0 = fdup(w.x), w1 = fdup(w.y), w2 = fdup(w.z), w3 = fdup(w.w);
                acc[0][0] = f2fma(xa.x, w0, acc[0][0]); acc[0][1] = f2fma(xa.y, w0, acc[0][1]);
                acc[0][2] = f2fma(xb2.x, w0, acc[0][2]); acc[0][3] = f2fma(xb2.y, w0, acc[0][3]);
                acc[1][0] = f2fma(xa.x, w1, acc[1][0]); acc[1][1] = f2fma(xa.y, w1, acc[1][1]);
                acc[1][2] = f2fma(xb2.x, w1, acc[1][2]); acc[1][3] = f2fma(xb2.y, w1, acc[1][3]);
                acc[2][0] = f2fma(xa.x, w2, acc[2][0]); acc[2][1] = f2fma(xa.y, w2, acc[2][1]);
                acc[2][2] = f2fma(xb2.x, w2, acc[2][2]); acc[2][3] = f2fma(xb2.y, w2, acc[2][3]);
                acc[3][0] = f2fma(xa.x, w3, acc[3][0]); acc[3][1] = f2fma(xa.y, w3, acc[3][1]);
                acc[3][2] = f2fma(xb2.x, w3, acc[3][2]); acc[3][3] = f2fma(xb2.y, w3, acc[3][3]);
            }
            if (!g1_isV) {
                // k: transposed store kst[c][t]
                #pragma unroll
                for (int c = 0; c < 4; ++c) {
                    ulonglong2 s1; s1.x = acc[c][0]; s1.y = acc[c][1];
                    ulonglong2 s2; s2.x = acc[c][2]; s2.y = acc[c][3];
                    *(ulonglong2*)&kst[(g1_c0 + c) * XT + g1_r0]     = s1;
                    *(ulonglong2*)&kst[(g1_c0 + c) * XT + g1_r0 + 4] = s2;
                }
            } else {
                // v: row-major store vs[t][c]
                #pragma unroll
                for (int p = 0; p < 4; ++p) {
                    const float2 u0 = funpack(acc[0][p]);
                    const float2 u1 = funpack(acc[1][p]);
                    const float2 u2 = funpack(acc[2][p]);
                    const float2 u3 = funpack(acc[3][p]);
                    float4 r0; r0.x = u0.x; r0.y = u1.x; r0.z = u2.x; r0.w = u3.x;
                    float4 r1; r1.x = u0.y; r1.y = u1.y; r1.z = u2.y; r1.w = u3.y;
                    *(float4*)&vs[(g1_r0 + 2 * p)     * D_ + g1_c0] = r0;
                    *(float4*)&vs[(g1_r0 + 2 * p + 1) * D_ + g1_c0] = r1;
                }
            }
        }
        __syncthreads();

        // ---- attention scores: att_t[kt][hh*64+q] = (q.k)/8, 4kt x 4q tile ----
        {
            u64 acc[4][2];
            #pragma unroll
            for (int c = 0; c < 4; ++c) { acc[c][0] = 0ull; acc[c][1] = 0ull; }
            #pragma unroll 4
            for (int d = 0; d < 64; ++d) {
                const float4 kk = *(const float4*)&kst[(at_db + d) * XT + at_kt0];
                const ulonglong2 xq = *(const ulonglong2*)&xs[(at_db + d) * XT + at_q0];
                const u64 k0 = fdup(kk.x), k1 = fdup(kk.y), k2 = fdup(kk.z), k3 = fdup(kk.w);
                acc[0][0] = f2fma(xq.x, k0, acc[0][0]); acc[0][1] = f2fma(xq.y, k0, acc[0][1]);
                acc[1][0] = f2fma(xq.x, k1, acc[1][0]); acc[1][1] = f2fma(xq.y, k1, acc[1][1]);
                acc[2][0] = f2fma(xq.x, k2, acc[2][0]); acc[2][1] = f2fma(xq.y, k2, acc[2][1]);
                acc[3][0] = f2fma(xq.x, k3, acc[3][0]); acc[3][1] = f2fma(xq.y, k3, acc[3][1]);
            }
            const u64 sc = fdup(0.125f);
            #pragma unroll
            for (int c = 0; c < 4; ++c) {
                ulonglong2 st; st.x = f2mul(acc[c][0], sc); st.y = f2mul(acc[c][1], sc);
                *(ulonglong2*)&ar[(at_kt0 + c) * AT + at_db + at_q0] = st;
            }
        }
        __syncthreads();

        // ---- softmax over kt: 16 warps x 8 rows ----
        for (int r = wid * 8; r < wid * 8 + 8; ++r) {
            const float a0 = ar[lane * AT + r];
            const float a1 = ar[(lane + 32) * AT + r];
            float m = fmaxf(a0, a1);
            #pragma unroll
            for (int o = 16; o > 0; o >>= 1) m = fmaxf(m, __shfl_xor_sync(0xffffffffu, m, o));
            const float e0 = __expf(a0 - m);
            const float e1x = __expf(a1 - m);
            float s = e0 + e1x;
            #pragma unroll
            for (int o = 16; o > 0; o >>= 1) s += __shfl_xor_sync(0xffffffffu, s, o);
            const float inv = 1.0f / s;
            ar[lane * AT + r]        = e0 * inv;
            ar[(lane + 32) * AT + r] = e1x * inv;
        }
        __syncthreads();

        // ---- oGEMM: o_t[dc][t] = sum_kt att_t[kt][hh*64+t] * v[kt][dc] ----
        {
            u64 acc[4][2];
            #pragma unroll
            for (int c = 0; c < 4; ++c) { acc[c][0] = 0ull; acc[c][1] = 0ull; }
            #pragma unroll 4
            for (int kt = 0; kt < 64; ++kt) {
                const float4 vv = *(const float4*)&vs[kt * D_ + o_dc0];
                const ulonglong2 at2 = *(const ulonglong2*)&ar[kt * AT + o_rb];
                const u64 v0 = fdup(vv.x), v1 = fdup(vv.y), v2 = fdup(vv.z), v3 = fdup(vv.w);
                acc[0][0] = f2fma(at2.x, v0, acc[0][0]); acc[0][1] = f2fma(at2.y, v0, acc[0][1]);
                acc[1][0] = f2fma(at2.x, v1, acc[1][0]); acc[1][1] = f2fma(at2.y, v1, acc[1][1]);
                acc[2][0] = f2fma(at2.x, v2, acc[2][0]); acc[2][1] = f2fma(at2.y, v2, acc[2][1]);
                acc[3][0] = f2fma(at2.x, v3, acc[3][0]); acc[3][1] = f2fma(at2.y, v3, acc[3][1]);
            }
            #pragma unroll
            for (int c = 0; c < 4; ++c) {
                ulonglong2 st; st.x = acc[c][0]; st.y = acc[c][1];
                *(ulonglong2*)&kst[(o_dc0 + c) * XT + o_t0] = st;
            }
        }
        __syncthreads();

        const float* Wsh0 = Ws + (size_t)(e * 2 + 0) * D_ * D_;
        const float* Wsh1 = Ws + (size_t)(e * 2 + 1) * D_ * D_;
        const float* bsh0 = bs + (e * 2 + 0) * D_;
        const float* bsh1 = bs + (e * 2 + 1) * D_;

        // ---- GEMM2: o1 = relu(o @ Ws0 + bs0) -> ar as o1_t (32c x 16r/warp) ----
        {
            u64 a2[4][2];
            const float4 bb = *(const float4*)&bsh0[g2_c0];
            a2[0][0] = a2[0][1] = fdup(bb.x);
            a2[1][0] = a2[1][1] = fdup(bb.y);
            a2[2][0] = a2[2][1] = fdup(bb.z);
            a2[3][0] = a2[3][1] = fdup(bb.w);
            #pragma unroll 4
            for (int d = 0; d < D_; ++d) {
                const ulonglong2 ov = *(const ulonglong2*)&kst[d * XT + g2_row0];
                const float4 w = *(const float4*)&Wsh0[d * D_ + g2_c0];
                const u64 w0 = fdup(w.x), w1 = fdup(w.y), w2 = fdup(w.z), w3 = fdup(w.w);
                a2[0][0] = f2fma(ov.x, w0, a2[0][0]); a2[0][1] = f2fma(ov.y, w0, a2[0][1]);
                a2[1][0] = f2fma(ov.x, w1, a2[1][0]); a2[1][1] = f2fma(ov.y, w1, a2[1][1]);
                a2[2][0] = f2fma(ov.x, w2, a2[2][0]); a2[2][1] = f2fma(ov.y, w2, a2[2][1]);
                a2[3][0] = f2fma(ov.x, w3, a2[3][0]); a2[3][1] = f2fma(ov.y, w3, a2[3][1]);
            }
            #pragma unroll
            for (int c = 0; c < 4; ++c) {
                const float2 u0 = funpack(a2[c][0]);
                const float2 u1 = funpack(a2[c][1]);
                ulonglong2 st;
                st.x = fpack(fmaxf(u0.x, 0.f), fmaxf(u0.y, 0.f));
                st.y = fpack(fmaxf(u1.x, 0.f), fmaxf(u1.y, 0.f));
                *(ulonglong2*)&ar[(g2_c0 + c) * XT + g2_row0] = st;
            }
        }
        __syncthreads();

        // ---- GEMM3: out_e = o1 @ Ws1 + bs1 ; accv += g * exp(out_e) ----
        {
            u64 a3[4][2];
            const float4 bb = *(const float4*)&bsh1[g2_c0];
            a3[0][0] = a3[0][1] = fdup(bb.x);
            a3[1][0] = a3[1][1] = fdup(bb.y);
            a3[2][0] = a3[2][1] = fdup(bb.z);
            a3[3][0] = a3[3][1] = fdup(bb.w);
            #pragma unroll 4
            for (int d = 0; d < D_; ++d) {
                const ulonglong2 ov = *(const ulonglong2*)&ar[d * XT + g2_row0];
                const float4 w = *(const float4*)&Wsh1[d * D_ + g2_c0];
                const u64 w0 = fdup(w.x), w1 = fdup(w.y), w2 = fdup(w.z), w3 = fdup(w.w);
                a3[0][0] = f2fma(ov.x, w0, a3[0][0]); a3[0][1] = f2fma(ov.y, w0, a3[0][1]);
                a3[1][0] = f2fma(ov.x, w1, a3[1][0]); a3[1][1] = f2fma(ov.y, w1, a3[1][1]);
                a3[2][0] = f2fma(ov.x, w2, a3[2][0]); a3[2][1] = f2fma(ov.y, w2, a3[2][1]);
                a3[3][0] = f2fma(ov.x, w3, a3[3][0]); a3[3][1] = f2fma(ov.y, w3, a3[3][1]);
            }
            #pragma unroll
            for (int c = 0; c < 4; ++c) {
                const float2 u0 = funpack(a3[c][0]);
                const float2 u1 = funpack(a3[c][1]);
                accv[c][0] += g * __expf(u0.x);
                accv[c][1] += g * __expf(u0.y);
                accv[c][2] += g * __expf(u1.x);
                accv[c][3] += g * __expf(u1.y);
            }
        }
        __syncthreads();
    }

    // ---- combine epilogue: log(sum g*exp), EPS guard; STG.128 per row ----
    const float EPSF = 2.2204460492503131e-16f;
    #pragma unroll
    for (int r = 0; r < 4; ++r) {
        float v0 = accv[0][r]; if (v0 == 0.f) v0 = EPSF;
        float v1 = accv[1][r]; if (v1 == 0.f) v1 = EPSF;
        float v2 = accv[2][r]; if (v2 == 0.f) v2 = EPSF;
        float v3 = accv[3][r]; if (v3 == 0.f) v3 = EPSF;
        float4 o4;
        o4.x = __logf(v0); o4.y = __logf(v1); o4.z = __logf(v2); o4.w = __logf(v3);
        *(float4*)&out[(((size_t)b * T_ + g2_row0 + r) * N_ + n) * D_ + g2_c0] = o4;
    }
}

// ---------------------------------------------------------------------------
// launcher
// ---------------------------------------------------------------------------
extern "C" void kernel_launch(void* const* d_in, const int* in_sizes, int n_in,
                              void* d_out, int out_size) {
    const float* x  = (const float*)d_in[0];
    const float* Wg = (const float*)d_in[1];
    const float* Wd = (const float*)d_in[2];
    const float* bd = (const float*)d_in[3];
    const float* Ws = (const float*)d_in[4];
    const float* bs = (const float*)d_in[5];
    float* out = (float*)d_out;

    const int smem_bytes = 34304 * (int)sizeof(float); // 137216 B
    cudaFuncSetAttribute(moe_kernel, cudaFuncAttributeMaxDynamicSharedMemorySize, smem_bytes);

    gate_kernel<<<B_, 128>>>(x, Wg);
    dim3 grid(N_, B_);
    moe_kernel<<<grid, 512, smem_bytes>>>(x, Wd, bd, Ws, bs, out);
}